// round 2
// baseline (speedup 1.0000x reference)
#include <cuda_runtime.h>

#define FULL 0xffffffffu

// Scratch (static device globals — allocation-free).
__device__ float g_partial[2][64][4096];   // per-(group,b,l) head-reduction partials
__device__ float g_S[3][64][128];          // per-quarter dot partials S_q[b][i], q=0..2

__device__ __forceinline__ float tanh_approx(float v) {
    float r;
    asm("tanh.approx.f32 %0, %1;" : "=f"(r) : "f"(v));
    return r;
}

// ---------------------------------------------------------------------------
// K0: quarter partial dots  S_q[b][i] = sum_{j in quarter q} W1[i,j]*x[b,j]
// grid (8 batch-octets, 4 head-chunks of 32, 3 quarters), 512 threads.
// Each block reads its W1 slice ONCE for 8 batches (L2 traffic ~12 MB total).
// ---------------------------------------------------------------------------
__global__ __launch_bounds__(512, 1)
void nade_carry_kernel(const float* __restrict__ x,
                       const float* __restrict__ W1)
{
    __shared__ float xs[8 * 1024];             // 32 KB: 8 batch quarter-rows

    const int bo   = blockIdx.x;               // batch octet
    const int hg   = blockIdx.y;               // head chunk (32 heads)
    const int q    = blockIdx.z;               // quarter 0..2
    const int tid  = threadIdx.x;
    const int w    = tid >> 5;
    const int lane = tid & 31;

    const float4* x4  = reinterpret_cast<const float4*>(x);
    float4*       xs4 = reinterpret_cast<float4*>(xs);
    // Stage 8 batches' quarter rows (2048 float4, 4 iters).
    for (int idx = tid; idx < 2048; idx += 512) {
        const int nb = idx >> 8;
        const int r  = idx & 255;
        xs4[idx] = x4[(bo * 8 + nb) * 1024 + q * 256 + r];
    }
    __syncthreads();

    const float4* W1_4 = reinterpret_cast<const float4*>(W1);

    // Warp owns 2 heads; per head: 8 float4 chunks/lane over the 1024-j quarter.
    #pragma unroll
    for (int hh = 0; hh < 2; hh++) {
        const int i = hg * 32 + w * 2 + hh;
        float acc[8];
        #pragma unroll
        for (int nb = 0; nb < 8; nb++) acc[nb] = 0.f;

        #pragma unroll
        for (int c = 0; c < 8; c++) {
            const int j4 = c * 32 + lane;                   // within quarter
            const float4 w1v = W1_4[i * 1024 + q * 256 + j4];
            #pragma unroll
            for (int nb = 0; nb < 8; nb++) {
                const float4 xv = xs4[nb * 256 + j4];
                acc[nb] = fmaf(xv.x, w1v.x,
                          fmaf(xv.y, w1v.y,
                          fmaf(xv.z, w1v.z,
                          fmaf(xv.w, w1v.w, acc[nb]))));
            }
        }
        #pragma unroll
        for (int nb = 0; nb < 8; nb++) {
            float s = acc[nb];
            #pragma unroll
            for (int o = 16; o > 0; o >>= 1)
                s += __shfl_down_sync(FULL, s, o);
            if (lane == 0) g_S[q][bo * 8 + nb][i] = s;
        }
    }
}

// ---------------------------------------------------------------------------
// K1: scan + sigmoid + head reduction, 4 batches per block, quarter of j.
// grid (16 batch-quads, 2 head-groups, 4 j-quarters) = 128 blocks, 512 thr.
// Warp owns 4 heads x 4 batches; lane owns 4 consecutive j per tile of 128.
// 8 tiles cover the 1024-j quarter. W1/W2 loaded once per 4 batches.
// ---------------------------------------------------------------------------
__global__ __launch_bounds__(512, 1)
void nade_main_kernel(const float* __restrict__ x,
                      const float* __restrict__ W1,
                      const float* __restrict__ b1,
                      const float* __restrict__ W2)
{
    __shared__ float xs[4 * 1024];             // 16 KB: 4 batch quarter-rows
    __shared__ float red[16][4][128];          // 32 KB: warp partials (single buf)

    const int b0   = blockIdx.x * 4;
    const int g    = blockIdx.y;
    const int q    = blockIdx.z;
    const int tid  = threadIdx.x;
    const int w    = tid >> 5;
    const int lane = tid & 31;

    const float4* x4  = reinterpret_cast<const float4*>(x);
    float4*       xs4 = reinterpret_cast<float4*>(xs);
    for (int idx = tid; idx < 1024; idx += 512) {
        const int nb = idx >> 8;
        const int r  = idx & 255;
        xs4[idx] = x4[(b0 + nb) * 1024 + q * 256 + r];
    }
    __syncthreads();

    const int i0 = g * 64 + w * 4;

    // cb[h][nb] = 0.5 * (b1[i] + carry_from_previous_quarters + running prefix)
    float cb[16];
    #pragma unroll
    for (int h = 0; h < 4; h++) {
        const int i = i0 + h;
        float base = b1[i];
        for (int qq = 0; qq < q; qq++) {
            #pragma unroll
            for (int nb = 0; nb < 4; nb++) {
                // carry differs per batch; accumulate into per-(h,nb) below
            }
        }
        #pragma unroll
        for (int nb = 0; nb < 4; nb++) {
            float c = base;
            for (int qq = 0; qq < q; qq++) c += g_S[qq][b0 + nb][i];
            cb[h * 4 + nb] = 0.5f * c;
        }
    }

    const float4* W1_4 = reinterpret_cast<const float4*>(W1);
    const float4* W2_4 = reinterpret_cast<const float4*>(W2);

    for (int t = 0; t < 8; ++t) {
        const int j0 = t * 128;                      // within quarter
        const int jv = t * 32 + lane;                // float4 idx within quarter

        // x values for the 4 batches (reused across 4 heads).
        float4 xv[4];
        #pragma unroll
        for (int nb = 0; nb < 4; nb++) xv[nb] = xs4[nb * 256 + jv];

        float4 acc[4];
        #pragma unroll
        for (int nb = 0; nb < 4; nb++) acc[nb] = make_float4(0.f, 0.f, 0.f, 0.f);

        #pragma unroll
        for (int h = 0; h < 4; h++) {
            const int i = i0 + h;
            const float4 w1v = W1_4[i * 1024 + q * 256 + jv];
            const float4 w2v = W2_4[i * 1024 + q * 256 + jv];

            #pragma unroll
            for (int nb = 0; nb < 4; nb++) {
                // Inclusive per-lane prefix of the 4 products.
                const float s0 = xv[nb].x * w1v.x;
                const float s1 = fmaf(xv[nb].y, w1v.y, s0);
                const float s2 = fmaf(xv[nb].z, w1v.z, s1);
                const float s3 = fmaf(xv[nb].w, w1v.w, s2);

                // Warp inclusive scan of lane totals.
                float inc = s3;
                #pragma unroll
                for (int o = 1; o < 32; o <<= 1) {
                    const float v = __shfl_up_sync(FULL, inc, o);
                    if (lane >= o) inc += v;
                }
                const float base = inc - s3;         // exclusive lane base

                const float c2l = fmaf(0.5f, base, cb[h * 4 + nb]);
                const float a0 = c2l;
                const float a1 = fmaf(0.5f, s0, c2l);
                const float a2 = fmaf(0.5f, s1, c2l);
                const float a3 = fmaf(0.5f, s2, c2l);

                const float t0 = tanh_approx(a0);
                const float t1 = tanh_approx(a1);
                const float t2 = tanh_approx(a2);
                const float t3 = tanh_approx(a3);

                acc[nb].x = fmaf(fmaf(0.5f, t0, 0.5f), w2v.x, acc[nb].x);
                acc[nb].y = fmaf(fmaf(0.5f, t1, 0.5f), w2v.y, acc[nb].y);
                acc[nb].z = fmaf(fmaf(0.5f, t2, 0.5f), w2v.z, acc[nb].z);
                acc[nb].w = fmaf(fmaf(0.5f, t3, 0.5f), w2v.w, acc[nb].w);

                // Advance chain carry by this tile's total.
                const float tot = __shfl_sync(FULL, inc, 31);
                cb[h * 4 + nb] = fmaf(0.5f, tot, cb[h * 4 + nb]);
            }
        }

        // Stage partials: warp w, batch nb, 128 l values.
        #pragma unroll
        for (int nb = 0; nb < 4; nb++)
            reinterpret_cast<float4*>(&red[w][nb][0])[lane] = acc[nb];
        __syncthreads();

        // All 16 warps reduce: warp -> (batch w>>2, l-chunk w&3).
        {
            const int nbr = w >> 2;
            const int l   = (w & 3) * 32 + lane;
            float sum = 0.f;
            #pragma unroll
            for (int ww = 0; ww < 16; ++ww) sum += red[ww][nbr][l];
            g_partial[g][b0 + nbr][q * 1024 + j0 + l] = sum;
        }
        __syncthreads();   // protect red[] before next tile's stores
    }
}

// ---------------------------------------------------------------------------
// K2: combine group partials + b2, accurate final sigmoid (float4).
// ---------------------------------------------------------------------------
__global__ void nade_final_kernel(const float* __restrict__ b2,
                                  float* __restrict__ out)
{
    const int idx4 = blockIdx.x * blockDim.x + threadIdx.x;   // 0..65535
    const int b = idx4 >> 10;
    const int r = idx4 & 1023;
    const float4 p0 = reinterpret_cast<const float4*>(&g_partial[0][b][0])[r];
    const float4 p1 = reinterpret_cast<const float4*>(&g_partial[1][b][0])[r];
    const float4 bv = reinterpret_cast<const float4*>(b2)[r];
    float4 o;
    o.x = 1.0f / (1.0f + __expf(-(p0.x + p1.x + bv.x)));
    o.y = 1.0f / (1.0f + __expf(-(p0.y + p1.y + bv.y)));
    o.z = 1.0f / (1.0f + __expf(-(p0.z + p1.z + bv.z)));
    o.w = 1.0f / (1.0f + __expf(-(p0.w + p1.w + bv.w)));
    reinterpret_cast<float4*>(out)[idx4] = o;
}

extern "C" void kernel_launch(void* const* d_in, const int* in_sizes, int n_in,
                              void* d_out, int out_size)
{
    const float* x  = (const float*)d_in[0];
    const float* W1 = (const float*)d_in[1];
    const float* b1 = (const float*)d_in[2];
    const float* W2 = (const float*)d_in[3];
    const float* b2 = (const float*)d_in[4];

    nade_carry_kernel<<<dim3(8, 4, 3), 512>>>(x, W1);
    nade_main_kernel<<<dim3(16, 2, 4), 512>>>(x, W1, b1, W2);
    nade_final_kernel<<<256, 256>>>(b2, (float*)d_out);
}